// round 3
// baseline (speedup 1.0000x reference)
#include <cuda_runtime.h>
#include <cstdint>
#include <cstddef>

// Problem dims (fixed)
#define HD 1024
#define FD 3584
#define NE 8
#define RD 79
#define RP 96        // padded low-rank dim (multiple of 32)
#define TMAX 8192
#define AMAX (TMAX*2)

// ----------------------------------------------------------------------------
// Scratch (device globals)
// ----------------------------------------------------------------------------
__device__ __align__(16) float g_P1[(size_t)AMAX * RP];
__device__ __align__(16) float g_P3[(size_t)AMAX * RP];
__device__ __align__(16) float g_Q2[(size_t)AMAX * RP];
__device__ __align__(16) float g_gate[(size_t)AMAX * FD];
__device__ __align__(16) float g_up[(size_t)AMAX * FD];
__device__ __align__(16) float g_U1p[(size_t)NE * FD * RP];
__device__ __align__(16) float g_U3p[(size_t)NE * FD * RP];
__device__ __align__(16) float g_U2p[(size_t)NE * HD * RP];

__device__ int   g_counts[NE];
__device__ int   g_offsets[NE + 1];
__device__ int   g_cursor[NE];
__device__ int   g_tok[AMAX];
__device__ float g_w[AMAX];
__device__ int   g_sel[TMAX * 2];
__device__ float g_wt[TMAX * 2];

// ----------------------------------------------------------------------------
// helpers
// ----------------------------------------------------------------------------
__device__ __forceinline__ uint32_t f2tf32(float x) {
    uint32_t u;
    asm("cvt.rna.tf32.f32 %0, %1;" : "=r"(u) : "f"(x));
    return u;
}
__device__ __forceinline__ void cp_async16(uint32_t dst, const void* src) {
    asm volatile("cp.async.cg.shared.global [%0], [%1], 16;\n" :: "r"(dst), "l"(src));
}
#define CP_COMMIT() asm volatile("cp.async.commit_group;\n" ::: "memory")
#define CP_WAIT1()  asm volatile("cp.async.wait_group 1;\n" ::: "memory")

// ----------------------------------------------------------------------------
// K0: zero output + routing counters
// ----------------------------------------------------------------------------
__global__ void zero_kernel(float* __restrict__ out, size_t n) {
    size_t i = (size_t)blockIdx.x * blockDim.x + threadIdx.x;
    size_t stride = (size_t)gridDim.x * blockDim.x;
    for (; i < n; i += stride) out[i] = 0.0f;
    if (blockIdx.x == 0 && threadIdx.x < NE) {
        g_counts[threadIdx.x] = 0;
        g_cursor[threadIdx.x] = 0;
    }
}

// ----------------------------------------------------------------------------
// K1: router (fp32 exact)
// ----------------------------------------------------------------------------
__global__ void router_kernel(const float* __restrict__ x,
                              const float* __restrict__ gw,
                              float* __restrict__ logits_out) {
    int t = blockIdx.x;
    __shared__ float xs[HD];
    __shared__ float lg[NE];
    int tid = threadIdx.x;
    for (int i = tid; i < HD; i += 256) xs[i] = x[(size_t)t * HD + i];
    __syncthreads();
    int w = tid >> 5, lane = tid & 31;
    if (w < NE) {
        const float* grow = gw + (size_t)w * HD;
        float s = 0.0f;
        for (int k = lane; k < HD; k += 32) s += xs[k] * grow[k];
        #pragma unroll
        for (int o = 16; o > 0; o >>= 1) s += __shfl_xor_sync(0xffffffffu, s, o);
        if (lane == 0) lg[w] = s;
    }
    __syncthreads();
    if (tid == 0) {
        float l[NE], m = -1e30f;
        #pragma unroll
        for (int e = 0; e < NE; e++) {
            l[e] = lg[e];
            logits_out[(size_t)t * NE + e] = l[e];
            if (l[e] > m) m = l[e];
        }
        float p[NE];
        #pragma unroll
        for (int e = 0; e < NE; e++) p[e] = expf(l[e] - m);
        int i0 = 0;
        #pragma unroll
        for (int e = 1; e < NE; e++) if (p[e] > p[i0]) i0 = e;
        int i1 = (i0 == 0) ? 1 : 0;
        #pragma unroll
        for (int e = 0; e < NE; e++) {
            if (e == i0) continue;
            if (p[e] > p[i1]) i1 = e;
        }
        float p0 = p[i0], p1 = p[i1];
        float inv = 1.0f / (p0 + p1);
        g_sel[t * 2 + 0] = i0;  g_wt[t * 2 + 0] = p0 * inv;
        g_sel[t * 2 + 1] = i1;  g_wt[t * 2 + 1] = p1 * inv;
        atomicAdd(&g_counts[i0], 1);
        atomicAdd(&g_counts[i1], 1);
    }
}

__global__ void scan_kernel() {
    int off = 0;
    g_offsets[0] = 0;
    for (int e = 0; e < NE; e++) {
        off += g_counts[e];
        g_offsets[e + 1] = off;
        g_cursor[e] = g_offsets[e];
    }
}

__global__ void scatter_kernel(int T) {
    int t = blockIdx.x * blockDim.x + threadIdx.x;
    if (t >= T) return;
    #pragma unroll
    for (int j = 0; j < 2; j++) {
        int e = g_sel[t * 2 + j];
        int slot = atomicAdd(&g_cursor[e], 1);
        g_tok[slot] = t;
        g_w[slot] = g_wt[t * 2 + j];
    }
}

// ----------------------------------------------------------------------------
// pad kernel: rows of RD -> rows of RP, zero-padded
// ----------------------------------------------------------------------------
__global__ void pad_kernel(const float* __restrict__ src, float* __restrict__ dst, int rows) {
    long i = (long)blockIdx.x * blockDim.x + threadIdx.x;
    long total = (long)rows * RP;
    long stride = (long)gridDim.x * blockDim.x;
    for (; i < total; i += stride) {
        int r = (int)(i / RP), c = (int)(i % RP);
        dst[i] = (c < RD) ? src[(long)r * RD + c] : 0.0f;
    }
}

// ----------------------------------------------------------------------------
// TF32 tensor-core MoE GEMM, cp.async 3-stage pipeline, uniform K.
//   C[m,n] = sum_k A(row_m)[k] * B(e)[n,k]
//   A row = GATHER ? x[tok[ga]]*K1 : buf[ga]*K1 ; B per-expert [*, K1]
//   EPI 0: crow[n] = (n<NReal ? acc : 0)       (write full tile width)
//   EPI 2: crow[n] += acc                      (n<NReal)
//   EPI 3: atomicAdd(out[tok*HD+n], w*acc)     (n<NReal)
// ----------------------------------------------------------------------------
template <int BM, int BN, int WARPS_M, int WARPS_N, int K1, bool GATHER, int EPI>
__global__ __launch_bounds__(256, 1)
void gemm_tf32(const float* __restrict__ A1,
               const float* __restrict__ Bbase, size_t bs1,
               float* __restrict__ C, int ldc, int NReal,
               float* __restrict__ outp) {
    constexpr int BK = 32;
    constexpr int STAGES = 3;
    constexpr int NTHR = 256;
    constexpr int NKT = K1 / BK;
    constexpr int WM = BM / WARPS_M;
    constexpr int WN = BN / WARPS_N;
    constexpr int MT = WM / 16;
    constexpr int NTL = WN / 8;
    constexpr int LDA = BK + 4;                 // pad: conflict-free frag loads
    constexpr int STG = (BM + BN) * LDA;        // floats per stage
    constexpr int LA = BM * (BK / 4) / NTHR;    // 16B chunks per thread (A)
    constexpr int LB = BN * (BK / 4) / NTHR;    // (B)
    static_assert(BM * (BK / 4) % NTHR == 0 && BN * (BK / 4) % NTHR == 0, "tiles");

    const int e = blockIdx.z;
    const int base = g_offsets[e];
    const int cnt = g_offsets[e + 1] - base;
    const int m0 = blockIdx.y * BM;
    if (m0 >= cnt) return;
    const int n0 = blockIdx.x * BN;

    const float* B1 = Bbase + (size_t)e * bs1;

    extern __shared__ float dsm[];
    uint32_t sbase;
    asm("{ .reg .u64 t; cvta.to.shared.u64 t, %1; cvt.u32.u64 %0, t; }"
        : "=r"(sbase) : "l"(dsm));

    const int tid = threadIdx.x;
    const int lane = tid & 31;
    const int wid = tid >> 5;
    const int wm = wid % WARPS_M;
    const int wn = wid / WARPS_M;

    // per-thread cp.async metadata
    const float* aptr[LA];
    uint32_t aoff[LA];
    #pragma unroll
    for (int i = 0; i < LA; i++) {
        int idx = tid + i * NTHR;
        int row = idx >> 3;
        int c4 = (idx & 7) * 4;
        aoff[i] = sbase + (uint32_t)((row * LDA + c4) * 4);
        int m = m0 + row;
        int ga = base + ((m < cnt) ? m : 0);           // clamp (masked in epilogue)
        const float* rp = GATHER ? (A1 + (size_t)g_tok[ga] * K1)
                                 : (A1 + (size_t)ga * K1);
        aptr[i] = rp + c4;
    }
    const float* bptr[LB];
    uint32_t boff[LB];
    #pragma unroll
    for (int i = 0; i < LB; i++) {
        int idx = tid + i * NTHR;
        int row = idx >> 3;
        int c4 = (idx & 7) * 4;
        boff[i] = sbase + (uint32_t)((BM * LDA + row * LDA + c4) * 4);
        int n = n0 + row;
        int nn = (n < NReal) ? n : 0;                  // clamp (masked in epilogue)
        bptr[i] = B1 + (size_t)nn * K1 + c4;
    }

    auto issue_load = [&](int kt, int s) {
        const int kb = kt * BK;
        const uint32_t sb = (uint32_t)(s * STG * 4);
        #pragma unroll
        for (int i = 0; i < LA; i++) cp_async16(aoff[i] + sb, aptr[i] + kb);
        #pragma unroll
        for (int i = 0; i < LB; i++) cp_async16(boff[i] + sb, bptr[i] + kb);
    };

    float acc[MT][NTL][4];
    #pragma unroll
    for (int mt = 0; mt < MT; mt++)
        #pragma unroll
        for (int nt = 0; nt < NTL; nt++)
            #pragma unroll
            for (int j = 0; j < 4; j++) acc[mt][nt][j] = 0.f;

    // prologue: stages 0..STAGES-2
    #pragma unroll
    for (int s = 0; s < STAGES - 1; s++) {
        if (s < NKT) issue_load(s, s);
        CP_COMMIT();
    }

    for (int kt = 0; kt < NKT; kt++) {
        CP_WAIT1();
        __syncthreads();
        int nk = kt + STAGES - 1;
        if (nk < NKT) issue_load(nk, nk % STAGES);
        CP_COMMIT();

        const float* As = dsm + (kt % STAGES) * STG;
        const float* Bs = As + BM * LDA;
        #pragma unroll
        for (int ks = 0; ks < BK / 8; ks++) {
            const int k0 = ks * 8 + (lane & 3);
            uint32_t afr[MT][4];
            uint32_t bfr[NTL][2];
            #pragma unroll
            for (int mt = 0; mt < MT; mt++) {
                int m = wm * WM + mt * 16 + (lane >> 2);
                afr[mt][0] = f2tf32(As[m * LDA + k0]);
                afr[mt][1] = f2tf32(As[(m + 8) * LDA + k0]);
                afr[mt][2] = f2tf32(As[m * LDA + k0 + 4]);
                afr[mt][3] = f2tf32(As[(m + 8) * LDA + k0 + 4]);
            }
            #pragma unroll
            for (int nt = 0; nt < NTL; nt++) {
                int n = wn * WN + nt * 8 + (lane >> 2);
                bfr[nt][0] = f2tf32(Bs[n * LDA + k0]);
                bfr[nt][1] = f2tf32(Bs[n * LDA + k0 + 4]);
            }
            #pragma unroll
            for (int mt = 0; mt < MT; mt++)
                #pragma unroll
                for (int nt = 0; nt < NTL; nt++) {
                    asm volatile(
                        "mma.sync.aligned.m16n8k8.row.col.f32.tf32.tf32.f32 "
                        "{%0,%1,%2,%3}, {%4,%5,%6,%7}, {%8,%9}, {%0,%1,%2,%3};\n"
                        : "+f"(acc[mt][nt][0]), "+f"(acc[mt][nt][1]),
                          "+f"(acc[mt][nt][2]), "+f"(acc[mt][nt][3])
                        : "r"(afr[mt][0]), "r"(afr[mt][1]),
                          "r"(afr[mt][2]), "r"(afr[mt][3]),
                          "r"(bfr[nt][0]), "r"(bfr[nt][1]));
                }
        }
        __syncthreads();
    }

    // epilogue
    #pragma unroll
    for (int mt = 0; mt < MT; mt++) {
        #pragma unroll
        for (int h = 0; h < 2; h++) {
            int ml = wm * WM + mt * 16 + (lane >> 2) + h * 8;
            int m = m0 + ml;
            if (m >= cnt) continue;
            int ga = base + m;
            if (EPI == 0 || EPI == 2) {
                float* crow = C + (size_t)ga * ldc;
                #pragma unroll
                for (int nt = 0; nt < NTL; nt++) {
                    #pragma unroll
                    for (int j = 0; j < 2; j++) {
                        int n = n0 + wn * WN + nt * 8 + 2 * (lane & 3) + j;
                        float v = acc[mt][nt][h * 2 + j];
                        if (EPI == 0) crow[n] = (n < NReal) ? v : 0.0f;
                        else if (n < NReal) crow[n] += v;
                    }
                }
            } else {
                int tok = g_tok[ga];
                float wgt = g_w[ga];
                float* orow = outp + (size_t)tok * HD;
                #pragma unroll
                for (int nt = 0; nt < NTL; nt++) {
                    #pragma unroll
                    for (int j = 0; j < 2; j++) {
                        int n = n0 + wn * WN + nt * 8 + 2 * (lane & 3) + j;
                        if (n < NReal) atomicAdd(&orow[n], wgt * acc[mt][nt][h * 2 + j]);
                    }
                }
            }
        }
    }
}

// ----------------------------------------------------------------------------
// Hact = silu(gate) * up
// ----------------------------------------------------------------------------
__global__ void silu_mul_kernel(float* __restrict__ g, const float* __restrict__ u, size_t n) {
    size_t i = (size_t)blockIdx.x * blockDim.x + threadIdx.x;
    size_t stride = (size_t)gridDim.x * blockDim.x;
    for (; i < n; i += stride) {
        float gv = g[i];
        float s = 1.0f / (1.0f + expf(-gv));
        g[i] = gv * s * u[i];
    }
}

// ----------------------------------------------------------------------------
// kernel_launch
// ----------------------------------------------------------------------------
extern "C" void kernel_launch(void* const* d_in, const int* in_sizes, int n_in,
                              void* d_out, int out_size) {
    const float* x  = (const float*)d_in[0];
    const float* gw = (const float*)d_in[1];
    const float* W1 = (const float*)d_in[2];
    const float* W2 = (const float*)d_in[3];
    const float* W3 = (const float*)d_in[4];
    const float* U1 = (const float*)d_in[5];
    const float* V1 = (const float*)d_in[6];
    const float* U2 = (const float*)d_in[7];
    const float* V2 = (const float*)d_in[8];
    const float* U3 = (const float*)d_in[9];
    const float* V3 = (const float*)d_in[10];
    (void)n_in; (void)out_size;

    const int T = in_sizes[0] / HD;
    const int A = T * 2;

    float* out    = (float*)d_out;
    float* logits = out + (size_t)T * HD;

    // GEMM instantiations + dynamic smem sizes
    auto* gP  = gemm_tf32<128,  96, 4, 2, HD, true,  0>;   // P1/P3 = X@V^T
    auto* gM  = gemm_tf32<128, 128, 2, 4, HD, true,  0>;   // gate/up main
    auto* gLR = gemm_tf32<128, 128, 2, 4, RP, false, 2>;   // += P@U^T
    auto* gQ  = gemm_tf32<128,  96, 4, 2, FD, false, 0>;   // Q2 = H@V2^T
    auto* gD  = gemm_tf32<128, 128, 2, 4, FD, false, 3>;   // down main (atomic)
    auto* gDL = gemm_tf32<128, 128, 2, 4, RP, false, 3>;   // down lr (atomic)
    const int SM_BN128 = 3 * (128 + 128) * 36 * 4;   // 110592 B
    const int SM_BN96  = 3 * (128 +  96) * 36 * 4;   //  96768 B
    cudaFuncSetAttribute((const void*)gP,  cudaFuncAttributeMaxDynamicSharedMemorySize, SM_BN96);
    cudaFuncSetAttribute((const void*)gM,  cudaFuncAttributeMaxDynamicSharedMemorySize, SM_BN128);
    cudaFuncSetAttribute((const void*)gLR, cudaFuncAttributeMaxDynamicSharedMemorySize, SM_BN128);
    cudaFuncSetAttribute((const void*)gQ,  cudaFuncAttributeMaxDynamicSharedMemorySize, SM_BN96);
    cudaFuncSetAttribute((const void*)gD,  cudaFuncAttributeMaxDynamicSharedMemorySize, SM_BN128);
    cudaFuncSetAttribute((const void*)gDL, cudaFuncAttributeMaxDynamicSharedMemorySize, SM_BN128);

    zero_kernel<<<2048, 256>>>(out, (size_t)T * HD);
    router_kernel<<<T, 256>>>(x, gw, logits);
    scan_kernel<<<1, 1>>>();
    scatter_kernel<<<(T + 255) / 256, 256>>>(T);

    // pad U matrices to row stride 96 (zero-filled tail)
    pad_kernel<<<2048, 256>>>(U1, g_U1p, NE * FD);
    pad_kernel<<<2048, 256>>>(U3, g_U3p, NE * FD);
    pad_kernel<<<2048, 256>>>(U2, g_U2p, NE * HD);

    const int mt128 = (T + 127) / 128;

    // P1 = X@V1^T, P3 = X@V3^T  (N=79 -> stride 96, zero-padded)
    {
        dim3 grid(1, mt128, NE);
        gP<<<grid, 256, SM_BN96>>>(x, V1, (size_t)RD * HD, g_P1, RP, RD, nullptr);
        gP<<<grid, 256, SM_BN96>>>(x, V3, (size_t)RD * HD, g_P3, RP, RD, nullptr);
    }
    // gate = X@W1^T, up = X@W3^T
    {
        dim3 grid(FD / 128, mt128, NE);
        gM<<<grid, 256, SM_BN128>>>(x, W1, (size_t)FD * HD, g_gate, FD, FD, nullptr);
        gM<<<grid, 256, SM_BN128>>>(x, W3, (size_t)FD * HD, g_up,   FD, FD, nullptr);
    }
    // gate += P1@U1p^T, up += P3@U3p^T  (K=96)
    {
        dim3 grid(FD / 128, mt128, NE);
        gLR<<<grid, 256, SM_BN128>>>(g_P1, g_U1p, (size_t)FD * RP, g_gate, FD, FD, nullptr);
        gLR<<<grid, 256, SM_BN128>>>(g_P3, g_U3p, (size_t)FD * RP, g_up,   FD, FD, nullptr);
    }
    // Hact = silu(gate)*up
    silu_mul_kernel<<<4096, 256>>>(g_gate, g_up, (size_t)A * FD);

    // Q2 = H@V2^T  (K=3584, N=79 -> stride 96)
    {
        dim3 grid(1, mt128, NE);
        gQ<<<grid, 256, SM_BN96>>>(g_gate, V2, (size_t)RD * FD, g_Q2, RP, RD, nullptr);
    }
    // out += w*(H@W2^T)   (K=3584, N=1024, atomic)
    {
        dim3 grid(HD / 128, mt128, NE);
        gD<<<grid, 256, SM_BN128>>>(g_gate, W2, (size_t)HD * FD, nullptr, HD, HD, out);
    }
    // out += w*(Q2@U2p^T) (K=96, N=1024, atomic)
    {
        dim3 grid(HD / 128, mt128, NE);
        gDL<<<grid, 256, SM_BN128>>>(g_Q2, g_U2p, (size_t)HD * RP, nullptr, HD, HD, out);
    }
}